// round 4
// baseline (speedup 1.0000x reference)
#include <cuda_runtime.h>
#include <cstdint>

// ---------------------------------------------------------------------------
// AlignedMPNN: B=8, N=256, F=128, D=128
// Output: ret [8,256,128] followed by et [8,256,256,128]
// ---------------------------------------------------------------------------

#define Bq 8
#define Nn 256
#define Ff 128
#define Dd 128
#define M_ET (Bq * Nn * Nn)          // 524288
#define NROWS (Bq * (Nn + 1))        // 2056
#define N_TILES2 (M_ET / 256)        // 2048 tiles of 256 rows

// scratch for MPNN chain
__device__ float g_msg1[NROWS * Dd];
__device__ float g_msg2[NROWS * Dd];
__device__ float g_o1[NROWS * Dd];
__device__ float g_msgsout[Bq * Nn * Dd];

// ===========================================================================
// helpers
// ===========================================================================
__device__ __forceinline__ uint32_t smem_u32_of(const void* p) {
    uint32_t a;
    asm("{ .reg .u64 t; cvta.to.shared.u64 t, %1; cvt.u32.u64 %0, t; }" : "=r"(a) : "l"(p));
    return a;
}

#define STS128(a0, a1, a2, a3, addr) \
    asm volatile("st.shared.v4.b32 [%0], {%1, %2, %3, %4};" :: "r"(addr), "r"(a0), "r"(a1), "r"(a2), "r"(a3) : "memory")

#define LDSM4(r, addr) \
    asm volatile("ldmatrix.sync.aligned.m8n8.x4.shared.b16 {%0,%1,%2,%3}, [%4];" \
        : "=r"((r)[0]), "=r"((r)[1]), "=r"((r)[2]), "=r"((r)[3]) : "r"(addr))

#define LDSM2(r, addr) \
    asm volatile("ldmatrix.sync.aligned.m8n8.x2.shared.b16 {%0,%1}, [%2];" \
        : "=r"((r)[0]), "=r"((r)[1]) : "r"(addr))

#define MMA_BF16(d, a, b) \
    asm volatile("mma.sync.aligned.m16n8k16.row.col.f32.bf16.bf16.f32 " \
        "{%0,%1,%2,%3}, {%4,%5,%6,%7}, {%8,%9}, {%0,%1,%2,%3};" \
        : "+f"((d)[0]), "+f"((d)[1]), "+f"((d)[2]), "+f"((d)[3]) \
        : "r"((a)[0]), "r"((a)[1]), "r"((a)[2]), "r"((a)[3]), "r"((b)[0]), "r"((b)[1]))

// XOR-swizzled byte offset for [row][unit] layout with 32B rows (2x16B units).
// Conflict-free for ldmatrix phases and STS128 (verified: 8 rows x fixed unit
// map to 8 distinct 16B segments mod 128B).
#define ASWZ(r, u) (((((r) * 2 + (u)) ^ (((r) >> 2) & 1))) * 16)

// bf16 two-term split of a pair of f32: packed hi (bf16x2) and lo (bf16x2)
__device__ __forceinline__ void split2(float x0, float x1, uint32_t& hi2, uint32_t& lo2) {
    asm("cvt.rn.bf16x2.f32 %0, %1, %2;" : "=r"(hi2) : "f"(x1), "f"(x0));
    float h0 = __uint_as_float(hi2 << 16);
    float h1 = __uint_as_float(hi2 & 0xffff0000u);
    float r0 = x0 - h0;
    float r1 = x1 - h1;
    asm("cvt.rn.bf16x2.f32 %0, %1, %2;" : "=r"(lo2) : "f"(r1), "f"(r0));
}

// ===========================================================================
// et GEMM: C[M,128] = A1[M,0:128k] @ W[0:128,:] + A2[M,0:128k] @ W[128:256,:] + be
// mma.sync bf16 3-term split (hh + lh + hl), persistent grid, 512 threads,
// M-tile = 256, warp grid 4x4 (64x32 per warp).
//
// smem:
//   W: 16 k16-chunks: chunk c hi at c*8192, lo at c*8192+4096.
//      layout [n=0..127][u=0..1] 16B units, XOR swizzle ASWZ.
//   A: OFF_A + buf*16384: hi at +0 (256 rows x 32B), lo at +8192. ASWZ rows.
// ===========================================================================
#define OFF_A   131072
#define SMEM_ET 163840

__global__ __launch_bounds__(512, 1)
void et_mma_kernel(const float* __restrict__ A1,
                   const float* __restrict__ A2,
                   const float* __restrict__ W,     // [256,128] f32
                   const float* __restrict__ bias,  // [128]
                   float* __restrict__ C)           // [M,128]
{
    extern __shared__ char smem[];
    const uint32_t sb = smem_u32_of(smem);
    const int tid   = threadIdx.x;
    const int lane  = tid & 31;
    const int wid   = tid >> 5;
    const int warpM = wid >> 2;      // 0..3  -> rows warpM*64
    const int warpN = wid & 3;       // 0..3  -> cols warpN*32

    // ---- one-time W conversion into resident smem (bf16 hi/lo, [n][k]) ----
    {
        const int n  = tid & 127;
        const int ks = (tid >> 7) * 8;          // 4 groups of 8 kk-units
#pragma unroll
        for (int u = 0; u < 8; ++u) {
            const int kk = ks + u;              // 8-k group index 0..31
            float w[8];
#pragma unroll
            for (int j = 0; j < 8; ++j) w[j] = W[(kk * 8 + j) * 128 + n];
            uint32_t h[4], l[4];
#pragma unroll
            for (int j = 0; j < 4; ++j) split2(w[2 * j], w[2 * j + 1], h[j], l[j]);
            const uint32_t a = sb + (uint32_t)((kk >> 1) * 8192 + ASWZ(n, kk & 1));
            STS128(h[0], h[1], h[2], h[3], a);
            STS128(l[0], l[1], l[2], l[3], a + 4096);
        }
    }

    // ---- per-thread invariant addressing ----
    // ldmatrix A (x4): mats (m0-7,k0-7),(m8-15,k0-7),(m0-7,k8-15),(m8-15,k8-15)
    const int mat   = lane >> 3;
    const int m_off = (mat & 1) * 8 + (lane & 7);
    const int ah    = mat >> 1;
    const uint32_t aoff0 = (uint32_t)ASWZ(warpM * 64 + m_off, ah);   // +mt*512 per mt

    // ldmatrix B (x2): 16 lanes -> rows n, unit u
    const int ls = lane & 15;
    const uint32_t boff0 = (uint32_t)ASWZ(warpN * 32 + (ls & 7), ls >> 3);  // +nt*256

    float2 biasv[4];
#pragma unroll
    for (int nt = 0; nt < 4; ++nt)
        biasv[nt] = *(const float2*)&bias[warpN * 32 + nt * 8 + (lane & 3) * 2];

    // A global-load + convert mapping: 2 threads per row (512 threads, 256 rows)
    const int row  = tid >> 1;
    const int half = tid & 1;
    const uint32_t soff = (uint32_t)ASWZ(row, half);
    const int goff = row * 128 + half * 8;

    __syncthreads();

    int tile = blockIdx.x;
    float4 v0, v1;
    if (tile < N_TILES2) {
        const float* p = A1 + (size_t)tile * 32768 + goff;
        v0 = *(const float4*)p;
        v1 = *(const float4*)(p + 4);
    }

    while (tile < N_TILES2) {
        float acc[4][4][4];
#pragma unroll
        for (int mt = 0; mt < 4; ++mt)
#pragma unroll
            for (int nt = 0; nt < 4; ++nt) {
                acc[mt][nt][0] = biasv[nt].x; acc[mt][nt][1] = biasv[nt].y;
                acc[mt][nt][2] = biasv[nt].x; acc[mt][nt][3] = biasv[nt].y;
            }

#pragma unroll 1
        for (int c = 0; c < 16; ++c) {
            const int buf = c & 1;

            // convert prefetched chunk -> smem buf
            {
                uint32_t h0, h1, h2, h3, l0, l1, l2, l3;
                split2(v0.x, v0.y, h0, l0);
                split2(v0.z, v0.w, h1, l1);
                split2(v1.x, v1.y, h2, l2);
                split2(v1.z, v1.w, h3, l3);
                const uint32_t sa = sb + OFF_A + buf * 16384 + soff;
                STS128(h0, h1, h2, h3, sa);
                STS128(l0, l1, l2, l3, sa + 8192);
            }
            __syncthreads();

            // prefetch next chunk (possibly next tile's chunk 0)
            {
                int ntile = tile, nc = c + 1;
                if (nc == 16) { ntile += gridDim.x; nc = 0; }
                if (ntile < N_TILES2) {
                    const float* base = (nc < 8) ? A1 : A2;
                    const float* p = base + (size_t)ntile * 32768 + goff + (nc & 7) * 16;
                    v0 = *(const float4*)p;
                    v1 = *(const float4*)(p + 4);
                }
            }

            // compute: hh, lh, hl
            const uint32_t wb = sb + (uint32_t)(c * 8192);
            const uint32_t ab = sb + OFF_A + buf * 16384;
            uint32_t Ah[4][4], Al[4][4], Bv[4][2];
#pragma unroll
            for (int mt = 0; mt < 4; ++mt) LDSM4(Ah[mt], ab + aoff0 + mt * 512);
#pragma unroll
            for (int nt = 0; nt < 4; ++nt) LDSM2(Bv[nt], wb + boff0 + nt * 256);
#pragma unroll
            for (int mt = 0; mt < 4; ++mt)
#pragma unroll
                for (int nt = 0; nt < 4; ++nt) MMA_BF16(acc[mt][nt], Ah[mt], Bv[nt]);
#pragma unroll
            for (int mt = 0; mt < 4; ++mt) LDSM4(Al[mt], ab + 8192 + aoff0 + mt * 512);
#pragma unroll
            for (int mt = 0; mt < 4; ++mt)
#pragma unroll
                for (int nt = 0; nt < 4; ++nt) MMA_BF16(acc[mt][nt], Al[mt], Bv[nt]);
#pragma unroll
            for (int nt = 0; nt < 4; ++nt) LDSM2(Bv[nt], wb + 4096 + boff0 + nt * 256);
#pragma unroll
            for (int mt = 0; mt < 4; ++mt)
#pragma unroll
                for (int nt = 0; nt < 4; ++nt) MMA_BF16(acc[mt][nt], Ah[mt], Bv[nt]);
        }

        // epilogue: direct STG (32B-sector aligned float2 stores)
        const size_t m0 = (size_t)tile * 256;
#pragma unroll
        for (int mt = 0; mt < 4; ++mt) {
            const size_t r0 = m0 + warpM * 64 + mt * 16 + (lane >> 2);
#pragma unroll
            for (int nt = 0; nt < 4; ++nt) {
                const int col = warpN * 32 + nt * 8 + (lane & 3) * 2;
                *(float2*)&C[r0 * 128 + col]       = make_float2(acc[mt][nt][0], acc[mt][nt][1]);
                *(float2*)&C[(r0 + 8) * 128 + col] = make_float2(acc[mt][nt][2], acc[mt][nt][3]);
            }
        }
        tile += gridDim.x;
    }
}

// ===========================================================================
// Kernel 2: msg1/msg2/o1 = nt @ {W_m1,W_m2,W_o1} + bias
// ===========================================================================
__global__ __launch_bounds__(128)
void msgs_gemm_kernel(const float* __restrict__ node,
                      const float* __restrict__ hidden,
                      const float* __restrict__ Wm1, const float* __restrict__ bm1,
                      const float* __restrict__ Wm2, const float* __restrict__ bm2,
                      const float* __restrict__ Wo1, const float* __restrict__ bo1)
{
    __shared__ float s[8][2 * Ff];
    const int r0  = blockIdx.x * 8;
    const int tid = threadIdx.x;

#pragma unroll
    for (int r = 0; r < 8; ++r) {
        int rowi = r0 + r;
        int b = rowi / (Nn + 1);
        int i = rowi % (Nn + 1);
        float v1 = 0.f, v2 = 0.f;
        if (i < Nn) {
            v1 = node[(b * Nn + i) * Ff + tid];
            v2 = hidden[(b * Nn + i) * Ff + tid];
        }
        s[r][tid]      = v1;
        s[r][Ff + tid] = v2;
    }
    __syncthreads();

    float a1[8], a2[8], a3[8];
    float bb1 = bm1[tid], bb2 = bm2[tid], bb3 = bo1[tid];
#pragma unroll
    for (int r = 0; r < 8; ++r) { a1[r] = bb1; a2[r] = bb2; a3[r] = bb3; }

    for (int k = 0; k < 2 * Ff; ++k) {
        float w1 = Wm1[k * Dd + tid];
        float w2 = Wm2[k * Dd + tid];
        float w3 = Wo1[k * Dd + tid];
#pragma unroll
        for (int r = 0; r < 8; ++r) {
            float sv = s[r][k];
            a1[r] = fmaf(sv, w1, a1[r]);
            a2[r] = fmaf(sv, w2, a2[r]);
            a3[r] = fmaf(sv, w3, a3[r]);
        }
    }
#pragma unroll
    for (int r = 0; r < 8; ++r) {
        int rowi = r0 + r;
        g_msg1[rowi * Dd + tid] = a1[r];
        g_msg2[rowi * Dd + tid] = a2[r];
        g_o1[rowi * Dd + tid]   = a3[r];
    }
}

// ===========================================================================
// Kernel 3: masked max over senders + add msg1.
// Block = (b, 8 destination columns). Each msg2 row loaded ONCE, reused for
// 8 destinations via bitmask + predicated fmax. Grid = 8*32 = 256 blocks.
// ===========================================================================
__global__ __launch_bounds__(128)
void maxred_kernel(const int* __restrict__ adj)
{
    __shared__ int mask[Nn];
    const int bj  = blockIdx.x;          // 0..255
    const int b   = bj >> 5;
    const int j0  = (bj & 31) * 8;
    const int tid = threadIdx.x;

    // build 8-bit adjacency mask per sender i (2 senders per thread)
#pragma unroll
    for (int s = 0; s < 2; ++s) {
        const int i = tid * 2 + s;
        const int* p = adj + ((size_t)(b * Nn + i) * Nn + j0);
        int4 a = *(const int4*)p;
        int4 c = *(const int4*)(p + 4);
        int m = 0;
        m |= (a.x > 0) << 0; m |= (a.y > 0) << 1; m |= (a.z > 0) << 2; m |= (a.w > 0) << 3;
        m |= (c.x > 0) << 4; m |= (c.y > 0) << 5; m |= (c.z > 0) << 6; m |= (c.w > 0) << 7;
        mask[i] = m;
    }
    __syncthreads();

    const float* m2 = g_msg2 + (size_t)(b * (Nn + 1)) * Dd + tid;
    const float vvirt = m2[Nn * Dd];     // virtual node always connected
    float vj[8];
#pragma unroll
    for (int q = 0; q < 8; ++q) vj[q] = vvirt;

#pragma unroll 4
    for (int i = 0; i < Nn; ++i) {
        const float x = m2[i * Dd];
        const int mk = mask[i];
#pragma unroll
        for (int q = 0; q < 8; ++q)
            if (mk & (1 << q)) vj[q] = fmaxf(vj[q], x);
    }

#pragma unroll
    for (int q = 0; q < 8; ++q) {
        const int j = j0 + q;
        g_msgsout[(size_t)(b * Nn + j) * Dd + tid] =
            g_msg1[(size_t)(b * (Nn + 1) + j) * Dd + tid] + vj[q];
    }
}

// ===========================================================================
// Kernel 4: ret = o1 + msgsout @ W_o2 + b_o2
// ===========================================================================
__global__ __launch_bounds__(128)
void final_gemm_kernel(const float* __restrict__ Wo2,
                       const float* __restrict__ bo2,
                       float* __restrict__ out)
{
    __shared__ float s[8][Dd];
    const int r0  = blockIdx.x * 8;
    const int tid = threadIdx.x;

#pragma unroll
    for (int r = 0; r < 8; ++r) s[r][tid] = g_msgsout[(r0 + r) * Dd + tid];
    __syncthreads();

    float acc[8];
    float bb = bo2[tid];
#pragma unroll
    for (int r = 0; r < 8; ++r) {
        int rowi = r0 + r;
        int b = rowi >> 8, j = rowi & 255;
        acc[r] = g_o1[(b * (Nn + 1) + j) * Dd + tid] + bb;
    }
    for (int k = 0; k < Dd; ++k) {
        float w = Wo2[k * Dd + tid];
#pragma unroll
        for (int r = 0; r < 8; ++r) acc[r] = fmaf(s[r][k], w, acc[r]);
    }
#pragma unroll
    for (int r = 0; r < 8; ++r) out[(r0 + r) * Dd + tid] = acc[r];
}

// ===========================================================================
extern "C" void kernel_launch(void* const* d_in, const int* in_sizes, int n_in,
                              void* d_out, int out_size)
{
    const float* node_fts = (const float*)d_in[0];
    const float* edge_fts = (const float*)d_in[1];
    const int*   adj_mat  = (const int*)d_in[3];
    const float* hidden   = (const float*)d_in[4];
    const float* e_hidden = (const float*)d_in[5];
    const float* We   = (const float*)d_in[6];
    const float* be   = (const float*)d_in[7];
    const float* W_m1 = (const float*)d_in[8];
    const float* b_m1 = (const float*)d_in[9];
    const float* W_m2 = (const float*)d_in[10];
    const float* b_m2 = (const float*)d_in[11];
    const float* W_o1 = (const float*)d_in[12];
    const float* b_o1 = (const float*)d_in[13];
    const float* W_o2 = (const float*)d_in[14];
    const float* b_o2 = (const float*)d_in[15];

    float* ret_out = (float*)d_out;
    float* et_out  = (float*)d_out + Bq * Nn * Dd;

    cudaFuncSetAttribute(et_mma_kernel, cudaFuncAttributeMaxDynamicSharedMemorySize, SMEM_ET);

    // MPNN chain (small)
    msgs_gemm_kernel<<<NROWS / 8, 128>>>(node_fts, hidden,
                                         W_m1, b_m1, W_m2, b_m2, W_o1, b_o1);
    maxred_kernel<<<Bq * Nn / 8, 128>>>(adj_mat);
    final_gemm_kernel<<<(Bq * Nn) / 8, 128>>>(W_o2, b_o2, ret_out);

    // Big et GEMM on tensor cores (persistent, mma.sync bf16-split)
    et_mma_kernel<<<148, 512, SMEM_ET>>>(edge_fts, e_hidden, We, be, et_out);
}

// round 5
// speedup vs baseline: 1.3144x; 1.3144x over previous
#include <cuda_runtime.h>
#include <cstdint>

// ---------------------------------------------------------------------------
// AlignedMPNN: B=8, N=256, F=128, D=128
// Output: ret [8,256,128] followed by et [8,256,256,128]
// ---------------------------------------------------------------------------

#define Bq 8
#define Nn 256
#define Ff 128
#define Dd 128
#define M_ET (Bq * Nn * Nn)          // 524288
#define NROWS (Bq * (Nn + 1))        // 2056
#define N_TILES2 (M_ET / 256)        // 2048 tiles of 256 rows

// scratch for MPNN chain
__device__ float g_msg1[NROWS * Dd];
__device__ float g_msg2[NROWS * Dd];
__device__ float g_o1[NROWS * Dd];

// ===========================================================================
// helpers
// ===========================================================================
__device__ __forceinline__ uint32_t smem_u32_of(const void* p) {
    uint32_t a;
    asm("{ .reg .u64 t; cvta.to.shared.u64 t, %1; cvt.u32.u64 %0, t; }" : "=r"(a) : "l"(p));
    return a;
}

#define STS128(a0, a1, a2, a3, addr) \
    asm volatile("st.shared.v4.b32 [%0], {%1, %2, %3, %4};" :: "r"(addr), "r"(a0), "r"(a1), "r"(a2), "r"(a3) : "memory")

#define LDSM4(r, addr) \
    asm volatile("ldmatrix.sync.aligned.m8n8.x4.shared.b16 {%0,%1,%2,%3}, [%4];" \
        : "=r"((r)[0]), "=r"((r)[1]), "=r"((r)[2]), "=r"((r)[3]) : "r"(addr))

#define LDSM2(r, addr) \
    asm volatile("ldmatrix.sync.aligned.m8n8.x2.shared.b16 {%0,%1}, [%2];" \
        : "=r"((r)[0]), "=r"((r)[1]) : "r"(addr))

#define MMA_F16(d, a, b) \
    asm volatile("mma.sync.aligned.m16n8k16.row.col.f32.f16.f16.f32 " \
        "{%0,%1,%2,%3}, {%4,%5,%6,%7}, {%8,%9}, {%0,%1,%2,%3};" \
        : "+f"((d)[0]), "+f"((d)[1]), "+f"((d)[2]), "+f"((d)[3]) \
        : "r"((a)[0]), "r"((a)[1]), "r"((a)[2]), "r"((a)[3]), "r"((b)[0]), "r"((b)[1]))

// XOR-swizzled byte offset for [row][unit] layout, 32B rows (2x16B units).
// Conflict-free for ldmatrix phases and STS128 (verified in R3/R4).
#define ASWZ(r, u) (((((r) * 2 + (u)) ^ (((r) >> 2) & 1))) * 16)

// pack two f32 -> f16x2 (x0 in low half)
__device__ __forceinline__ uint32_t cvt2h(float x0, float x1) {
    uint32_t r;
    asm("cvt.rn.f16x2.f32 %0, %1, %2;" : "=r"(r) : "f"(x1), "f"(x0));
    return r;
}

// fp16 two-term split of a pair of f32: packed hi (f16x2) and lo (f16x2)
__device__ __forceinline__ void split2h(float x0, float x1, uint32_t& hi2, uint32_t& lo2) {
    asm("cvt.rn.f16x2.f32 %0, %1, %2;" : "=r"(hi2) : "f"(x1), "f"(x0));
    float h0, h1;
    asm("{.reg .b16 l, h;\n\t"
        "mov.b32 {l, h}, %2;\n\t"
        "cvt.f32.f16 %0, l;\n\t"
        "cvt.f32.f16 %1, h;}" : "=f"(h0), "=f"(h1) : "r"(hi2));
    float r0 = x0 - h0;
    float r1 = x1 - h1;
    asm("cvt.rn.f16x2.f32 %0, %1, %2;" : "=r"(lo2) : "f"(r1), "f"(r0));
}

// ===========================================================================
// et GEMM: C[M,128] = A1[M,0:128k] @ W[0:128,:] + A2[M,0:128k] @ W[128:256,:] + be
// mma.sync fp16 2-term split (A_f16 * W_hi + A_f16 * W_lo), persistent grid,
// 512 threads, M-tile = 256, warp grid 4x4 (64x32 per warp).
//
// smem:
//   W: 16 k16-chunks: chunk c hi at c*8192, lo at c*8192+4096.
//      layout [n=0..127][u=0..1] 16B units, XOR swizzle ASWZ.
//   A: OFF_A + buf*8192: 256 rows x 32B (fp16), ASWZ rows. double buffered.
// ===========================================================================
#define OFF_A   131072
#define SMEM_ET 147456

__global__ __launch_bounds__(512, 1)
void et_mma_kernel(const float* __restrict__ A1,
                   const float* __restrict__ A2,
                   const float* __restrict__ W,     // [256,128] f32
                   const float* __restrict__ bias,  // [128]
                   float* __restrict__ C)           // [M,128]
{
    extern __shared__ char smem[];
    const uint32_t sb = smem_u32_of(smem);
    const int tid   = threadIdx.x;
    const int lane  = tid & 31;
    const int wid   = tid >> 5;
    const int warpM = wid >> 2;      // 0..3  -> rows warpM*64
    const int warpN = wid & 3;       // 0..3  -> cols warpN*32

    // ---- one-time W conversion into resident smem (fp16 hi/lo, [n][k]) ----
    {
        const int n  = tid & 127;
        const int ks = (tid >> 7) * 8;          // 4 groups of 8 kk-units
#pragma unroll
        for (int u = 0; u < 8; ++u) {
            const int kk = ks + u;              // 8-k group index 0..31
            float w[8];
#pragma unroll
            for (int j = 0; j < 8; ++j) w[j] = W[(kk * 8 + j) * 128 + n];
            uint32_t h[4], l[4];
#pragma unroll
            for (int j = 0; j < 4; ++j) split2h(w[2 * j], w[2 * j + 1], h[j], l[j]);
            const uint32_t a = sb + (uint32_t)((kk >> 1) * 8192 + ASWZ(n, kk & 1));
            STS128(h[0], h[1], h[2], h[3], a);
            STS128(l[0], l[1], l[2], l[3], a + 4096);
        }
    }

    // ---- per-thread invariant addressing ----
    // ldmatrix A (x4): mats (m0-7,k0-7),(m8-15,k0-7),(m0-7,k8-15),(m8-15,k8-15)
    const int mat   = lane >> 3;
    const int m_off = (mat & 1) * 8 + (lane & 7);
    const int ah    = mat >> 1;
    const uint32_t aoff0 = (uint32_t)ASWZ(warpM * 64 + m_off, ah);   // +mt*512 per mt

    // ldmatrix B (x2): 16 lanes -> rows n, unit u
    const int ls = lane & 15;
    const uint32_t boff0 = (uint32_t)ASWZ(warpN * 32 + (ls & 7), ls >> 3);  // +nt*256

    float2 biasv[4];
#pragma unroll
    for (int nt = 0; nt < 4; ++nt)
        biasv[nt] = *(const float2*)&bias[warpN * 32 + nt * 8 + (lane & 3) * 2];

    // A global-load + convert mapping: 2 threads per row (512 threads, 256 rows)
    const int row  = tid >> 1;
    const int half = tid & 1;
    const uint32_t soff = (uint32_t)ASWZ(row, half);
    const int goff = row * 128 + half * 8;

    __syncthreads();

    int tile = blockIdx.x;
    float4 v0, v1;
    if (tile < N_TILES2) {
        const float* p = A1 + (size_t)tile * 32768 + goff;
        v0 = *(const float4*)p;
        v1 = *(const float4*)(p + 4);
    }

    while (tile < N_TILES2) {
        float acc[4][4][4];
#pragma unroll
        for (int mt = 0; mt < 4; ++mt)
#pragma unroll
            for (int nt = 0; nt < 4; ++nt) {
                acc[mt][nt][0] = biasv[nt].x; acc[mt][nt][1] = biasv[nt].y;
                acc[mt][nt][2] = biasv[nt].x; acc[mt][nt][3] = biasv[nt].y;
            }

#pragma unroll 1
        for (int c = 0; c < 16; ++c) {
            const int buf = c & 1;

            // convert prefetched chunk -> smem buf (single fp16)
            {
                uint32_t p0 = cvt2h(v0.x, v0.y);
                uint32_t p1 = cvt2h(v0.z, v0.w);
                uint32_t p2 = cvt2h(v1.x, v1.y);
                uint32_t p3 = cvt2h(v1.z, v1.w);
                STS128(p0, p1, p2, p3, sb + OFF_A + buf * 8192 + soff);
            }
            __syncthreads();

            // prefetch next chunk (possibly next tile's chunk 0)
            {
                int ntile = tile, nc = c + 1;
                if (nc == 16) { ntile += gridDim.x; nc = 0; }
                if (ntile < N_TILES2) {
                    const float* base = (nc < 8) ? A1 : A2;
                    const float* p = base + (size_t)ntile * 32768 + goff + (nc & 7) * 16;
                    v0 = *(const float4*)p;
                    v1 = *(const float4*)(p + 4);
                }
            }

            // compute: A*W_hi + A*W_lo
            const uint32_t wb = sb + (uint32_t)(c * 8192);
            const uint32_t ab = sb + OFF_A + buf * 8192;
            uint32_t Av[4][4], Bv[4][2];
#pragma unroll
            for (int mt = 0; mt < 4; ++mt) LDSM4(Av[mt], ab + aoff0 + mt * 512);
#pragma unroll
            for (int nt = 0; nt < 4; ++nt) LDSM2(Bv[nt], wb + boff0 + nt * 256);
#pragma unroll
            for (int mt = 0; mt < 4; ++mt)
#pragma unroll
                for (int nt = 0; nt < 4; ++nt) MMA_F16(acc[mt][nt], Av[mt], Bv[nt]);
#pragma unroll
            for (int nt = 0; nt < 4; ++nt) LDSM2(Bv[nt], wb + 4096 + boff0 + nt * 256);
#pragma unroll
            for (int mt = 0; mt < 4; ++mt)
#pragma unroll
                for (int nt = 0; nt < 4; ++nt) MMA_F16(acc[mt][nt], Av[mt], Bv[nt]);
        }

        // epilogue: direct STG (32B-sector aligned float2 stores)
        const size_t m0 = (size_t)tile * 256;
#pragma unroll
        for (int mt = 0; mt < 4; ++mt) {
            const size_t r0 = m0 + warpM * 64 + mt * 16 + (lane >> 2);
#pragma unroll
            for (int nt = 0; nt < 4; ++nt) {
                const int col = warpN * 32 + nt * 8 + (lane & 3) * 2;
                *(float2*)&C[r0 * 128 + col]       = make_float2(acc[mt][nt][0], acc[mt][nt][1]);
                *(float2*)&C[(r0 + 8) * 128 + col] = make_float2(acc[mt][nt][2], acc[mt][nt][3]);
            }
        }
        tile += gridDim.x;
    }
}

// ===========================================================================
// Kernel 2: msg1/msg2/o1 = nt @ {W_m1,W_m2,W_o1} + bias
// ===========================================================================
__global__ __launch_bounds__(128)
void msgs_gemm_kernel(const float* __restrict__ node,
                      const float* __restrict__ hidden,
                      const float* __restrict__ Wm1, const float* __restrict__ bm1,
                      const float* __restrict__ Wm2, const float* __restrict__ bm2,
                      const float* __restrict__ Wo1, const float* __restrict__ bo1)
{
    __shared__ float s[8][2 * Ff];
    const int r0  = blockIdx.x * 8;
    const int tid = threadIdx.x;

#pragma unroll
    for (int r = 0; r < 8; ++r) {
        int rowi = r0 + r;
        int b = rowi / (Nn + 1);
        int i = rowi % (Nn + 1);
        float v1 = 0.f, v2 = 0.f;
        if (i < Nn) {
            v1 = node[(b * Nn + i) * Ff + tid];
            v2 = hidden[(b * Nn + i) * Ff + tid];
        }
        s[r][tid]      = v1;
        s[r][Ff + tid] = v2;
    }
    __syncthreads();

    float a1[8], a2[8], a3[8];
    float bb1 = bm1[tid], bb2 = bm2[tid], bb3 = bo1[tid];
#pragma unroll
    for (int r = 0; r < 8; ++r) { a1[r] = bb1; a2[r] = bb2; a3[r] = bb3; }

    for (int k = 0; k < 2 * Ff; ++k) {
        float w1 = Wm1[k * Dd + tid];
        float w2 = Wm2[k * Dd + tid];
        float w3 = Wo1[k * Dd + tid];
#pragma unroll
        for (int r = 0; r < 8; ++r) {
            float sv = s[r][k];
            a1[r] = fmaf(sv, w1, a1[r]);
            a2[r] = fmaf(sv, w2, a2[r]);
            a3[r] = fmaf(sv, w3, a3[r]);
        }
    }
#pragma unroll
    for (int r = 0; r < 8; ++r) {
        int rowi = r0 + r;
        g_msg1[rowi * Dd + tid] = a1[r];
        g_msg2[rowi * Dd + tid] = a2[r];
        g_o1[rowi * Dd + tid]   = a3[r];
    }
}

// ===========================================================================
// Kernel 3 (fused): masked max over senders + add msg1, then
//   ret = o1 + msgs @ W_o2 + b_o2.
// Block = (b, 8 destination columns). msg2 rows loaded once, reused for 8
// destinations via bitmask + predicated fmax; msgs kept in smem for the GEMM.
// ===========================================================================
__global__ __launch_bounds__(128)
void maxfinal_kernel(const int* __restrict__ adj,
                     const float* __restrict__ Wo2,
                     const float* __restrict__ bo2,
                     float* __restrict__ out)      // [B*N,128]
{
    __shared__ int mask[Nn];
    __shared__ float ms[8][Dd];
    const int bj  = blockIdx.x;          // 0..255
    const int b   = bj >> 5;
    const int j0  = (bj & 31) * 8;
    const int tid = threadIdx.x;

    // build 8-bit adjacency mask per sender i (2 senders per thread)
#pragma unroll
    for (int s = 0; s < 2; ++s) {
        const int i = tid * 2 + s;
        const int* p = adj + ((size_t)(b * Nn + i) * Nn + j0);
        int4 a = *(const int4*)p;
        int4 c = *(const int4*)(p + 4);
        int m = 0;
        m |= (a.x > 0) << 0; m |= (a.y > 0) << 1; m |= (a.z > 0) << 2; m |= (a.w > 0) << 3;
        m |= (c.x > 0) << 4; m |= (c.y > 0) << 5; m |= (c.z > 0) << 6; m |= (c.w > 0) << 7;
        mask[i] = m;
    }
    __syncthreads();

    const float* m2 = g_msg2 + (size_t)(b * (Nn + 1)) * Dd + tid;
    const float vvirt = m2[Nn * Dd];     // virtual node always connected
    float vj[8];
#pragma unroll
    for (int q = 0; q < 8; ++q) vj[q] = vvirt;

#pragma unroll 4
    for (int i = 0; i < Nn; ++i) {
        const float x = m2[i * Dd];
        const int mk = mask[i];
#pragma unroll
        for (int q = 0; q < 8; ++q)
            if (mk & (1 << q)) vj[q] = fmaxf(vj[q], x);
    }

#pragma unroll
    for (int q = 0; q < 8; ++q)
        ms[q][tid] = g_msg1[(size_t)(b * (Nn + 1) + j0 + q) * Dd + tid] + vj[q];
    __syncthreads();

    // final GEMM: out = o1 + ms @ Wo2 + bo2
    float acc[8];
    const float bb = bo2[tid];
#pragma unroll
    for (int r = 0; r < 8; ++r)
        acc[r] = g_o1[(size_t)(b * (Nn + 1) + j0 + r) * Dd + tid] + bb;

    for (int k = 0; k < Dd; ++k) {
        const float w = Wo2[k * Dd + tid];
#pragma unroll
        for (int r = 0; r < 8; ++r) acc[r] = fmaf(ms[r][k], w, acc[r]);
    }
#pragma unroll
    for (int r = 0; r < 8; ++r)
        out[(size_t)(b * Nn + j0 + r) * Dd + tid] = acc[r];
}

// ===========================================================================
extern "C" void kernel_launch(void* const* d_in, const int* in_sizes, int n_in,
                              void* d_out, int out_size)
{
    const float* node_fts = (const float*)d_in[0];
    const float* edge_fts = (const float*)d_in[1];
    const int*   adj_mat  = (const int*)d_in[3];
    const float* hidden   = (const float*)d_in[4];
    const float* e_hidden = (const float*)d_in[5];
    const float* We   = (const float*)d_in[6];
    const float* be   = (const float*)d_in[7];
    const float* W_m1 = (const float*)d_in[8];
    const float* b_m1 = (const float*)d_in[9];
    const float* W_m2 = (const float*)d_in[10];
    const float* b_m2 = (const float*)d_in[11];
    const float* W_o1 = (const float*)d_in[12];
    const float* b_o1 = (const float*)d_in[13];
    const float* W_o2 = (const float*)d_in[14];
    const float* b_o2 = (const float*)d_in[15];

    float* ret_out = (float*)d_out;
    float* et_out  = (float*)d_out + Bq * Nn * Dd;

    cudaFuncSetAttribute(et_mma_kernel, cudaFuncAttributeMaxDynamicSharedMemorySize, SMEM_ET);

    // MPNN chain (small)
    msgs_gemm_kernel<<<NROWS / 8, 128>>>(node_fts, hidden,
                                         W_m1, b_m1, W_m2, b_m2, W_o1, b_o1);
    maxfinal_kernel<<<Bq * Nn / 8, 128>>>(adj_mat, W_o2, b_o2, ret_out);

    // Big et GEMM on tensor cores (persistent, mma.sync fp16 2-term split)
    et_mma_kernel<<<148, 512, SMEM_ET>>>(edge_fts, e_hidden, We, be, et_out);
}

// round 6
// speedup vs baseline: 2.0617x; 1.5686x over previous
#include <cuda_runtime.h>
#include <cstdint>

// ---------------------------------------------------------------------------
// AlignedMPNN: B=8, N=256, F=128, D=128
// Output: ret [8,256,128] followed by et [8,256,256,128]
// ---------------------------------------------------------------------------

#define Bq 8
#define Nn 256
#define Ff 128
#define Dd 128
#define M_ET (Bq * Nn * Nn)          // 524288
#define NROWS (Bq * (Nn + 1))        // 2056
#define N_TILES2 (M_ET / 256)        // 2048 tiles of 256 rows

// scratch for MPNN chain
__device__ float g_msg1[NROWS * Dd];
__device__ float g_msg2[NROWS * Dd];
__device__ float g_o1[NROWS * Dd];

// ===========================================================================
// helpers
// ===========================================================================
__device__ __forceinline__ uint32_t smem_u32_of(const void* p) {
    uint32_t a;
    asm("{ .reg .u64 t; cvta.to.shared.u64 t, %1; cvt.u32.u64 %0, t; }" : "=r"(a) : "l"(p));
    return a;
}

#define STS128(a0, a1, a2, a3, addr) \
    asm volatile("st.shared.v4.b32 [%0], {%1, %2, %3, %4};" :: "r"(addr), "r"(a0), "r"(a1), "r"(a2), "r"(a3) : "memory")

#define LDSM4(r, addr) \
    asm volatile("ldmatrix.sync.aligned.m8n8.x4.shared.b16 {%0,%1,%2,%3}, [%4];" \
        : "=r"((r)[0]), "=r"((r)[1]), "=r"((r)[2]), "=r"((r)[3]) : "r"(addr))

#define LDSM2(r, addr) \
    asm volatile("ldmatrix.sync.aligned.m8n8.x2.shared.b16 {%0,%1}, [%2];" \
        : "=r"((r)[0]), "=r"((r)[1]) : "r"(addr))

#define MMA_F16(d, a, b) \
    asm volatile("mma.sync.aligned.m16n8k16.row.col.f32.f16.f16.f32 " \
        "{%0,%1,%2,%3}, {%4,%5,%6,%7}, {%8,%9}, {%0,%1,%2,%3};" \
        : "+f"((d)[0]), "+f"((d)[1]), "+f"((d)[2]), "+f"((d)[3]) \
        : "r"((a)[0]), "r"((a)[1]), "r"((a)[2]), "r"((a)[3]), "r"((b)[0]), "r"((b)[1]))

// 64B-row layout: row r (64B apart), unit u (0..3, 16B each), XOR swizzle.
// seg = (4*(r&1) + (u ^ ((r>>1)&3))) mod 8 distinct across 8 rows per fixed u,
// and across STS128 quarter-warp phases (verified by enumeration).
#define ASWZ64(r, u) ((uint32_t)((r) * 64 + (((u) ^ (((r) >> 1) & 3)) * 16)))

// pack two f32 -> f16x2 (x0 in low half)
__device__ __forceinline__ uint32_t cvt2h(float x0, float x1) {
    uint32_t r;
    asm("cvt.rn.f16x2.f32 %0, %1, %2;" : "=r"(r) : "f"(x1), "f"(x0));
    return r;
}

// ===========================================================================
// et GEMM: C[M,128] = A1[M,128k] @ W[0:128,:] + A2[M,128k] @ W[128:256,:] + be
// mma.sync fp16 single-term (A_f16 * W_f16), persistent grid, 512 threads,
// M-tile = 256, warp grid 4x4 (64x32 per warp), k-chunks of 32.
//
// smem:
//   W: 8 k32-chunks, chunk c at c*8192: [n=0..127] rows of 64B (4 units), ASWZ64.
//   A: OFF_A + buf*16384: 256 rows x 64B, ASWZ64. double buffered.
// ===========================================================================
#define OFF_A   65536
#define SMEM_ET 98304

__global__ __launch_bounds__(512, 1)
void et_mma_kernel(const float* __restrict__ A1,
                   const float* __restrict__ A2,
                   const float* __restrict__ W,     // [256,128] f32
                   const float* __restrict__ bias,  // [128]
                   float* __restrict__ C)           // [M,128]
{
    extern __shared__ char smem[];
    const uint32_t sb = smem_u32_of(smem);
    const int tid   = threadIdx.x;
    const int lane  = tid & 31;
    const int wid   = tid >> 5;
    const int warpM = wid >> 2;      // 0..3  -> rows warpM*64
    const int warpN = wid & 3;       // 0..3  -> cols warpN*32

    // ---- one-time W conversion into resident smem (fp16, [n][k]) ----
    {
        const int n = tid & 127;
        const int g = tid >> 7;                 // 0..3
#pragma unroll
        for (int t = 0; t < 8; ++t) {
            const int kk = g * 8 + t;           // 8-k unit index 0..31
            const int c  = kk >> 2;
            const int u  = kk & 3;
            float w[8];
#pragma unroll
            for (int j = 0; j < 8; ++j) w[j] = W[(kk * 8 + j) * 128 + n];
            uint32_t p0 = cvt2h(w[0], w[1]);
            uint32_t p1 = cvt2h(w[2], w[3]);
            uint32_t p2 = cvt2h(w[4], w[5]);
            uint32_t p3 = cvt2h(w[6], w[7]);
            STS128(p0, p1, p2, p3, sb + c * 8192 + ASWZ64(n, u));
        }
    }

    // ---- per-thread invariant addressing ----
    // ldmatrix A (x4): mats (m0-7,klo),(m8-15,klo),(m0-7,khi),(m8-15,khi)
    const int mat  = lane >> 3;
    const int row0 = warpM * 64 + (mat & 1) * 8 + (lane & 7);
    const int ah   = mat >> 1;
    const int xr   = (row0 >> 1) & 3;
    uint32_t aoffs[2];
#pragma unroll
    for (int s = 0; s < 2; ++s)
        aoffs[s] = (uint32_t)(row0 * 64 + (((2 * s + ah) ^ xr) * 16));

    // ldmatrix B (x2)
    const int ls = lane & 15;
    const int n0 = warpN * 32 + (ls & 7);
    const int ub = ls >> 3;
    const int xn = (n0 >> 1) & 3;
    uint32_t boffs[2];
#pragma unroll
    for (int s = 0; s < 2; ++s)
        boffs[s] = (uint32_t)(n0 * 64 + (((2 * s + ub) ^ xn) * 16));

    float2 biasv[4];
#pragma unroll
    for (int nt = 0; nt < 4; ++nt)
        biasv[nt] = *(const float2*)&bias[warpN * 32 + nt * 8 + (lane & 3) * 2];

    // A global-load + convert mapping: 2 threads per row (512 threads, 256 rows)
    const int row  = tid >> 1;
    const int half = tid & 1;
    const uint32_t sa0 = ASWZ64(row, half * 2);
    const uint32_t sa1 = ASWZ64(row, half * 2 + 1);
    const int goff = row * 128 + half * 16;

    __syncthreads();

    int tile = blockIdx.x;
    float4 v0, v1, v2, v3;
    if (tile < N_TILES2) {
        const float* p = A1 + (size_t)tile * 32768 + goff;
        v0 = *(const float4*)p;
        v1 = *(const float4*)(p + 4);
        v2 = *(const float4*)(p + 8);
        v3 = *(const float4*)(p + 12);
    }

    while (tile < N_TILES2) {
        float acc[4][4][4];
#pragma unroll
        for (int mt = 0; mt < 4; ++mt)
#pragma unroll
            for (int nt = 0; nt < 4; ++nt) {
                acc[mt][nt][0] = biasv[nt].x; acc[mt][nt][1] = biasv[nt].y;
                acc[mt][nt][2] = biasv[nt].x; acc[mt][nt][3] = biasv[nt].y;
            }

#pragma unroll 1
        for (int c = 0; c < 8; ++c) {
            const int buf = c & 1;
            const uint32_t ab = sb + OFF_A + buf * 16384;

            // convert prefetched chunk -> smem buf (fp16)
            {
                uint32_t p0 = cvt2h(v0.x, v0.y), p1 = cvt2h(v0.z, v0.w);
                uint32_t p2 = cvt2h(v1.x, v1.y), p3 = cvt2h(v1.z, v1.w);
                uint32_t p4 = cvt2h(v2.x, v2.y), p5 = cvt2h(v2.z, v2.w);
                uint32_t p6 = cvt2h(v3.x, v3.y), p7 = cvt2h(v3.z, v3.w);
                STS128(p0, p1, p2, p3, ab + sa0);
                STS128(p4, p5, p6, p7, ab + sa1);
            }
            __syncthreads();

            // prefetch next chunk (possibly next tile's chunk 0)
            {
                int ntile = tile, nc = c + 1;
                if (nc == 8) { ntile += gridDim.x; nc = 0; }
                if (ntile < N_TILES2) {
                    const float* base = (nc < 4) ? A1 : A2;
                    const float* p = base + (size_t)ntile * 32768 + goff + (nc & 3) * 32;
                    v0 = *(const float4*)p;
                    v1 = *(const float4*)(p + 4);
                    v2 = *(const float4*)(p + 8);
                    v3 = *(const float4*)(p + 12);
                }
            }

            // compute: 2 k16 steps x 16 MMA
            const uint32_t wb = sb + (uint32_t)(c * 8192);
#pragma unroll
            for (int s = 0; s < 2; ++s) {
                uint32_t Av[4][4], Bv[4][2];
#pragma unroll
                for (int mt = 0; mt < 4; ++mt) LDSM4(Av[mt], ab + aoffs[s] + mt * 1024);
#pragma unroll
                for (int nt = 0; nt < 4; ++nt) LDSM2(Bv[nt], wb + boffs[s] + nt * 512);
#pragma unroll
                for (int mt = 0; mt < 4; ++mt)
#pragma unroll
                    for (int nt = 0; nt < 4; ++nt) MMA_F16(acc[mt][nt], Av[mt], Bv[nt]);
            }
        }

        // epilogue: direct STG (32B-sector aligned float2 stores)
        const size_t m0 = (size_t)tile * 256;
#pragma unroll
        for (int mt = 0; mt < 4; ++mt) {
            const size_t r0 = m0 + warpM * 64 + mt * 16 + (lane >> 2);
#pragma unroll
            for (int nt = 0; nt < 4; ++nt) {
                const int col = warpN * 32 + nt * 8 + (lane & 3) * 2;
                *(float2*)&C[r0 * 128 + col]       = make_float2(acc[mt][nt][0], acc[mt][nt][1]);
                *(float2*)&C[(r0 + 8) * 128 + col] = make_float2(acc[mt][nt][2], acc[mt][nt][3]);
            }
        }
        tile += gridDim.x;
    }
}

// ===========================================================================
// Kernel 2: msg1/msg2/o1 = nt @ {W_m1,W_m2,W_o1} + bias.
// 512 threads: col = tid&127, k-quarter = tid>>7 (64 k each) -> smem reduce.
// ===========================================================================
__global__ __launch_bounds__(512)
void msgs_gemm_kernel(const float* __restrict__ node,
                      const float* __restrict__ hidden,
                      const float* __restrict__ Wm1, const float* __restrict__ bm1,
                      const float* __restrict__ Wm2, const float* __restrict__ bm2,
                      const float* __restrict__ Wo1, const float* __restrict__ bo1)
{
    __shared__ float s[8][2 * Ff];
    __shared__ float part[3][3][8][128];   // [kq-1][which][row][col]
    const int r0  = blockIdx.x * 8;
    const int tid = threadIdx.x;
    const int col = tid & 127;
    const int kq  = tid >> 7;

    for (int t = tid; t < 8 * 256; t += 512) {
        const int r = t >> 8, k = t & 255;
        const int rowi = r0 + r;
        const int b = rowi / (Nn + 1);
        const int i = rowi % (Nn + 1);
        float v = 0.f;
        if (i < Nn)
            v = (k < Ff) ? node[(b * Nn + i) * Ff + k]
                         : hidden[(b * Nn + i) * Ff + (k - Ff)];
        s[r][k] = v;
    }
    __syncthreads();

    float a1[8], a2[8], a3[8];
#pragma unroll
    for (int r = 0; r < 8; ++r) { a1[r] = 0.f; a2[r] = 0.f; a3[r] = 0.f; }

    const int kbase = kq * 64;
#pragma unroll 4
    for (int kk = 0; kk < 64; ++kk) {
        const int k = kbase + kk;
        const float w1 = Wm1[k * Dd + col];
        const float w2 = Wm2[k * Dd + col];
        const float w3 = Wo1[k * Dd + col];
#pragma unroll
        for (int r = 0; r < 8; ++r) {
            const float sv = s[r][k];
            a1[r] = fmaf(sv, w1, a1[r]);
            a2[r] = fmaf(sv, w2, a2[r]);
            a3[r] = fmaf(sv, w3, a3[r]);
        }
    }

    if (kq) {
#pragma unroll
        for (int r = 0; r < 8; ++r) {
            part[kq - 1][0][r][col] = a1[r];
            part[kq - 1][1][r][col] = a2[r];
            part[kq - 1][2][r][col] = a3[r];
        }
    }
    __syncthreads();

    if (kq == 0) {
        const float bb1 = bm1[col], bb2 = bm2[col], bb3 = bo1[col];
#pragma unroll
        for (int r = 0; r < 8; ++r) {
            float o1 = a1[r] + bb1, o2 = a2[r] + bb2, o3 = a3[r] + bb3;
#pragma unroll
            for (int q = 0; q < 3; ++q) {
                o1 += part[q][0][r][col];
                o2 += part[q][1][r][col];
                o3 += part[q][2][r][col];
            }
            const int rowi = r0 + r;
            g_msg1[rowi * Dd + col] = o1;
            g_msg2[rowi * Dd + col] = o2;
            g_o1[rowi * Dd + col]   = o3;
        }
    }
}

// ===========================================================================
// Kernel 3 (fused): masked max over senders + add msg1, then
//   ret = o1 + msgs @ W_o2 + b_o2.
// Block = (b, 4 destination cols), 512 blocks x 256 threads.
// i-range and k-range each split across the two 128-thread groups.
// ===========================================================================
__global__ __launch_bounds__(256)
void maxfinal_kernel(const int* __restrict__ adj,
                     const float* __restrict__ Wo2,
                     const float* __restrict__ bo2,
                     float* __restrict__ out)      // [B*N,128]
{
    __shared__ int mask[Nn];
    __shared__ float red[2][4][128];
    __shared__ float ms[4][128];
    __shared__ float pg[4][128];
    const int blk = blockIdx.x;          // 0..511
    const int b   = blk >> 6;
    const int j0  = (blk & 63) * 4;
    const int tid = threadIdx.x;
    const int d   = tid & 127;
    const int ih  = tid >> 7;

    // 4-bit adjacency mask per sender i
    {
        const int* p = adj + ((size_t)(b * Nn + tid) * Nn + j0);
        const int4 a = *(const int4*)p;
        mask[tid] = (a.x > 0) | ((a.y > 0) << 1) | ((a.z > 0) << 2) | ((a.w > 0) << 3);
    }
    __syncthreads();

    const float* m2 = g_msg2 + (size_t)(b * (Nn + 1)) * Dd + d;
    const float vv = m2[Nn * Dd];        // virtual node always connected
    float vj[4] = {vv, vv, vv, vv};

#pragma unroll 4
    for (int ii = 0; ii < 128; ++ii) {
        const int i = ih * 128 + ii;
        const float x = m2[i * Dd];
        const int mk = mask[i];
#pragma unroll
        for (int q = 0; q < 4; ++q)
            if (mk & (1 << q)) vj[q] = fmaxf(vj[q], x);
    }
#pragma unroll
    for (int q = 0; q < 4; ++q) red[ih][q][d] = vj[q];
    __syncthreads();

    if (ih == 0) {
#pragma unroll
        for (int q = 0; q < 4; ++q)
            ms[q][d] = g_msg1[(size_t)(b * (Nn + 1) + j0 + q) * Dd + d]
                     + fmaxf(red[0][q][d], red[1][q][d]);
    }
    __syncthreads();

    // GEMM: each half-group handles 64 k
    float acc[4] = {0.f, 0.f, 0.f, 0.f};
    const int kb = ih * 64;
#pragma unroll 4
    for (int kk = 0; kk < 64; ++kk) {
        const int k = kb + kk;
        const float w = Wo2[k * Dd + d];
#pragma unroll
        for (int q = 0; q < 4; ++q) acc[q] = fmaf(ms[q][k], w, acc[q]);
    }
    if (ih) {
#pragma unroll
        for (int q = 0; q < 4; ++q) pg[q][d] = acc[q];
    }
    __syncthreads();
    if (!ih) {
        const float bb = bo2[d];
#pragma unroll
        for (int q = 0; q < 4; ++q)
            out[(size_t)(b * Nn + j0 + q) * Dd + d] =
                acc[q] + pg[q][d] + g_o1[(size_t)(b * (Nn + 1) + j0 + q) * Dd + d] + bb;
    }
}

// ===========================================================================
extern "C" void kernel_launch(void* const* d_in, const int* in_sizes, int n_in,
                              void* d_out, int out_size)
{
    const float* node_fts = (const float*)d_in[0];
    const float* edge_fts = (const float*)d_in[1];
    const int*   adj_mat  = (const int*)d_in[3];
    const float* hidden   = (const float*)d_in[4];
    const float* e_hidden = (const float*)d_in[5];
    const float* We   = (const float*)d_in[6];
    const float* be   = (const float*)d_in[7];
    const float* W_m1 = (const float*)d_in[8];
    const float* b_m1 = (const float*)d_in[9];
    const float* W_m2 = (const float*)d_in[10];
    const float* b_m2 = (const float*)d_in[11];
    const float* W_o1 = (const float*)d_in[12];
    const float* b_o1 = (const float*)d_in[13];
    const float* W_o2 = (const float*)d_in[14];
    const float* b_o2 = (const float*)d_in[15];

    float* ret_out = (float*)d_out;
    float* et_out  = (float*)d_out + Bq * Nn * Dd;

    cudaFuncSetAttribute(et_mma_kernel, cudaFuncAttributeMaxDynamicSharedMemorySize, SMEM_ET);

    // MPNN chain (small)
    msgs_gemm_kernel<<<NROWS / 8, 512>>>(node_fts, hidden,
                                         W_m1, b_m1, W_m2, b_m2, W_o1, b_o1);
    maxfinal_kernel<<<Bq * Nn / 4, 256>>>(adj_mat, W_o2, b_o2, ret_out);

    // Big et GEMM on tensor cores (persistent, mma.sync fp16 single-term)
    et_mma_kernel<<<148, 512, SMEM_ET>>>(edge_fts, e_hidden, We, be, et_out);
}

// round 7
// speedup vs baseline: 2.2100x; 1.0719x over previous
#include <cuda_runtime.h>
#include <cstdint>

// ---------------------------------------------------------------------------
// AlignedMPNN: B=8, N=256, F=128, D=128
// Output: ret [8,256,128] followed by et [8,256,256,128]
// ---------------------------------------------------------------------------

#define Bq 8
#define Nn 256
#define Ff 128
#define Dd 128
#define M_ET (Bq * Nn * Nn)          // 524288
#define NROWS (Bq * (Nn + 1))        // 2056
#define N_TILES1 (M_ET / 128)        // 4096 tiles of 128 rows

// scratch for MPNN chain
__device__ float g_msg1[NROWS * Dd];
__device__ float g_msg2[NROWS * Dd];
__device__ float g_o1[NROWS * Dd];

// ===========================================================================
// helpers
// ===========================================================================
__device__ __forceinline__ uint32_t smem_u32_of(const void* p) {
    uint32_t a;
    asm("{ .reg .u64 t; cvta.to.shared.u64 t, %1; cvt.u32.u64 %0, t; }" : "=r"(a) : "l"(p));
    return a;
}

#define STS128(a0, a1, a2, a3, addr) \
    asm volatile("st.shared.v4.b32 [%0], {%1, %2, %3, %4};" :: "r"(addr), "r"(a0), "r"(a1), "r"(a2), "r"(a3) : "memory")

#define LDSM4(r, addr) \
    asm volatile("ldmatrix.sync.aligned.m8n8.x4.shared.b16 {%0,%1,%2,%3}, [%4];" \
        : "=r"((r)[0]), "=r"((r)[1]), "=r"((r)[2]), "=r"((r)[3]) : "r"(addr))

#define LDSM2(r, addr) \
    asm volatile("ldmatrix.sync.aligned.m8n8.x2.shared.b16 {%0,%1}, [%2];" \
        : "=r"((r)[0]), "=r"((r)[1]) : "r"(addr))

#define MMA_F16(d, a, b) \
    asm volatile("mma.sync.aligned.m16n8k16.row.col.f32.f16.f16.f32 " \
        "{%0,%1,%2,%3}, {%4,%5,%6,%7}, {%8,%9}, {%0,%1,%2,%3};" \
        : "+f"((d)[0]), "+f"((d)[1]), "+f"((d)[2]), "+f"((d)[3]) \
        : "r"((a)[0]), "r"((a)[1]), "r"((a)[2]), "r"((a)[3]), "r"((b)[0]), "r"((b)[1]))

// 64B-row layout: row r (64B apart), unit u (0..3, 16B each), XOR swizzle.
// Conflict-free for STS128 / ldmatrix phases (verified R6).
#define ASWZ64(r, u) ((uint32_t)((r) * 64 + (((u) ^ (((r) >> 1) & 3)) * 16)))

// pack two f32 -> f16x2 (x0 in low half)
__device__ __forceinline__ uint32_t cvt2h(float x0, float x1) {
    uint32_t r;
    asm("cvt.rn.f16x2.f32 %0, %1, %2;" : "=r"(r) : "f"(x1), "f"(x0));
    return r;
}

// ===========================================================================
// et GEMM: C[M,128] = A1[M,128k] @ W[0:128,:] + A2[M,128k] @ W[128:256,:] + be
// mma.sync fp16 single-term, persistent grid 296 CTAs x 256 threads,
// 2 CTAs/SM, M-tile = 128, warp grid 2x4 (64x32 per warp), k-chunks of 32.
//
// smem (per CTA, 80KB):
//   W: 8 k32-chunks, chunk c at c*8192: [n=0..127] rows of 64B, ASWZ64.
//   A: OFF_A + buf*8192: 128 rows x 64B, ASWZ64. double buffered.
// ===========================================================================
#define OFF_A   65536
#define SMEM_ET 81920

__global__ __launch_bounds__(256, 2)
void et_mma_kernel(const float* __restrict__ A1,
                   const float* __restrict__ A2,
                   const float* __restrict__ W,     // [256,128] f32
                   const float* __restrict__ bias,  // [128]
                   float* __restrict__ C)           // [M,128]
{
    extern __shared__ char smem[];
    const uint32_t sb = smem_u32_of(smem);
    const int tid   = threadIdx.x;
    const int lane  = tid & 31;
    const int wid   = tid >> 5;
    const int warpM = wid >> 2;      // 0..1  -> rows warpM*64
    const int warpN = wid & 3;       // 0..3  -> cols warpN*32

    // ---- one-time W conversion into resident smem (fp16, [n][k]) ----
    {
        const int n = tid & 127;
        const int g = tid >> 7;                 // 0..1
#pragma unroll
        for (int t = 0; t < 16; ++t) {
            const int kk = g * 16 + t;          // 8-k unit index 0..31
            const int c  = kk >> 2;
            const int u  = kk & 3;
            float w[8];
#pragma unroll
            for (int j = 0; j < 8; ++j) w[j] = W[(kk * 8 + j) * 128 + n];
            uint32_t p0 = cvt2h(w[0], w[1]);
            uint32_t p1 = cvt2h(w[2], w[3]);
            uint32_t p2 = cvt2h(w[4], w[5]);
            uint32_t p3 = cvt2h(w[6], w[7]);
            STS128(p0, p1, p2, p3, sb + c * 8192 + ASWZ64(n, u));
        }
    }

    // ---- per-thread invariant addressing ----
    // ldmatrix A (x4): mats (m0-7,klo),(m8-15,klo),(m0-7,khi),(m8-15,khi)
    const int mat  = lane >> 3;
    const int row0 = warpM * 64 + (mat & 1) * 8 + (lane & 7);
    const int ah   = mat >> 1;
    const int xr   = (row0 >> 1) & 3;
    uint32_t aoffs[2];
#pragma unroll
    for (int s = 0; s < 2; ++s)
        aoffs[s] = (uint32_t)(row0 * 64 + (((2 * s + ah) ^ xr) * 16));

    // ldmatrix B (x2)
    const int ls = lane & 15;
    const int n0 = warpN * 32 + (ls & 7);
    const int ub = ls >> 3;
    const int xn = (n0 >> 1) & 3;
    uint32_t boffs[2];
#pragma unroll
    for (int s = 0; s < 2; ++s)
        boffs[s] = (uint32_t)(n0 * 64 + (((2 * s + ub) ^ xn) * 16));

    float2 biasv[4];
#pragma unroll
    for (int nt = 0; nt < 4; ++nt)
        biasv[nt] = *(const float2*)&bias[warpN * 32 + nt * 8 + (lane & 3) * 2];

    // A global-load + convert mapping: 2 threads per row (256 threads, 128 rows)
    const int row  = tid >> 1;
    const int half = tid & 1;
    const uint32_t sa0 = ASWZ64(row, half * 2);
    const uint32_t sa1 = ASWZ64(row, half * 2 + 1);
    const int goff = row * 128 + half * 16;

    __syncthreads();

    int tile = blockIdx.x;
    float4 v0, v1, v2, v3;
    if (tile < N_TILES1) {
        const float* p = A1 + (size_t)tile * 16384 + goff;
        v0 = *(const float4*)p;
        v1 = *(const float4*)(p + 4);
        v2 = *(const float4*)(p + 8);
        v3 = *(const float4*)(p + 12);
    }

    while (tile < N_TILES1) {
        float acc[4][4][4];
#pragma unroll
        for (int mt = 0; mt < 4; ++mt)
#pragma unroll
            for (int nt = 0; nt < 4; ++nt) {
                acc[mt][nt][0] = biasv[nt].x; acc[mt][nt][1] = biasv[nt].y;
                acc[mt][nt][2] = biasv[nt].x; acc[mt][nt][3] = biasv[nt].y;
            }

#pragma unroll 1
        for (int c = 0; c < 8; ++c) {
            const int buf = c & 1;
            const uint32_t ab = sb + OFF_A + buf * 8192;

            // convert prefetched chunk -> smem buf (fp16)
            {
                uint32_t p0 = cvt2h(v0.x, v0.y), p1 = cvt2h(v0.z, v0.w);
                uint32_t p2 = cvt2h(v1.x, v1.y), p3 = cvt2h(v1.z, v1.w);
                uint32_t p4 = cvt2h(v2.x, v2.y), p5 = cvt2h(v2.z, v2.w);
                uint32_t p6 = cvt2h(v3.x, v3.y), p7 = cvt2h(v3.z, v3.w);
                STS128(p0, p1, p2, p3, ab + sa0);
                STS128(p4, p5, p6, p7, ab + sa1);
            }
            __syncthreads();

            // prefetch next chunk (possibly next tile's chunk 0)
            {
                int ntile = tile, nc = c + 1;
                if (nc == 8) { ntile += gridDim.x; nc = 0; }
                if (ntile < N_TILES1) {
                    const float* base = (nc < 4) ? A1 : A2;
                    const float* p = base + (size_t)ntile * 16384 + goff + (nc & 3) * 32;
                    v0 = *(const float4*)p;
                    v1 = *(const float4*)(p + 4);
                    v2 = *(const float4*)(p + 8);
                    v3 = *(const float4*)(p + 12);
                }
            }

            // compute: 2 k16 steps x 16 MMA
            const uint32_t wb = sb + (uint32_t)(c * 8192);
#pragma unroll
            for (int s = 0; s < 2; ++s) {
                uint32_t Av[4][4], Bv[4][2];
#pragma unroll
                for (int mt = 0; mt < 4; ++mt) LDSM4(Av[mt], ab + aoffs[s] + mt * 1024);
#pragma unroll
                for (int nt = 0; nt < 4; ++nt) LDSM2(Bv[nt], wb + boffs[s] + nt * 512);
#pragma unroll
                for (int mt = 0; mt < 4; ++mt)
#pragma unroll
                    for (int nt = 0; nt < 4; ++nt) MMA_F16(acc[mt][nt], Av[mt], Bv[nt]);
            }
        }

        // epilogue: direct STG (32B-sector aligned float2 stores)
        const size_t m0 = (size_t)tile * 128;
#pragma unroll
        for (int mt = 0; mt < 4; ++mt) {
            const size_t r0 = m0 + warpM * 64 + mt * 16 + (lane >> 2);
#pragma unroll
            for (int nt = 0; nt < 4; ++nt) {
                const int col = warpN * 32 + nt * 8 + (lane & 3) * 2;
                *(float2*)&C[r0 * 128 + col]       = make_float2(acc[mt][nt][0], acc[mt][nt][1]);
                *(float2*)&C[(r0 + 8) * 128 + col] = make_float2(acc[mt][nt][2], acc[mt][nt][3]);
            }
        }
        tile += gridDim.x;
    }
}

// ===========================================================================
// Kernel 2: msg1/msg2/o1 = nt @ {W_m1,W_m2,W_o1} + bias.
// 512 threads: col = tid&127, k-quarter = tid>>7 (64 k each) -> smem reduce.
// ===========================================================================
__global__ __launch_bounds__(512)
void msgs_gemm_kernel(const float* __restrict__ node,
                      const float* __restrict__ hidden,
                      const float* __restrict__ Wm1, const float* __restrict__ bm1,
                      const float* __restrict__ Wm2, const float* __restrict__ bm2,
                      const float* __restrict__ Wo1, const float* __restrict__ bo1)
{
    __shared__ float s[8][2 * Ff];
    __shared__ float part[3][3][8][128];   // [kq-1][which][row][col]
    const int r0  = blockIdx.x * 8;
    const int tid = threadIdx.x;
    const int col = tid & 127;
    const int kq  = tid >> 7;

    for (int t = tid; t < 8 * 256; t += 512) {
        const int r = t >> 8, k = t & 255;
        const int rowi = r0 + r;
        const int b = rowi / (Nn + 1);
        const int i = rowi % (Nn + 1);
        float v = 0.f;
        if (i < Nn)
            v = (k < Ff) ? node[(b * Nn + i) * Ff + k]
                         : hidden[(b * Nn + i) * Ff + (k - Ff)];
        s[r][k] = v;
    }
    __syncthreads();

    float a1[8], a2[8], a3[8];
#pragma unroll
    for (int r = 0; r < 8; ++r) { a1[r] = 0.f; a2[r] = 0.f; a3[r] = 0.f; }

    const int kbase = kq * 64;
#pragma unroll 4
    for (int kk = 0; kk < 64; ++kk) {
        const int k = kbase + kk;
        const float w1 = Wm1[k * Dd + col];
        const float w2 = Wm2[k * Dd + col];
        const float w3 = Wo1[k * Dd + col];
#pragma unroll
        for (int r = 0; r < 8; ++r) {
            const float sv = s[r][k];
            a1[r] = fmaf(sv, w1, a1[r]);
            a2[r] = fmaf(sv, w2, a2[r]);
            a3[r] = fmaf(sv, w3, a3[r]);
        }
    }

    if (kq) {
#pragma unroll
        for (int r = 0; r < 8; ++r) {
            part[kq - 1][0][r][col] = a1[r];
            part[kq - 1][1][r][col] = a2[r];
            part[kq - 1][2][r][col] = a3[r];
        }
    }
    __syncthreads();

    if (kq == 0) {
        const float bb1 = bm1[col], bb2 = bm2[col], bb3 = bo1[col];
#pragma unroll
        for (int r = 0; r < 8; ++r) {
            float o1 = a1[r] + bb1, o2 = a2[r] + bb2, o3 = a3[r] + bb3;
#pragma unroll
            for (int q = 0; q < 3; ++q) {
                o1 += part[q][0][r][col];
                o2 += part[q][1][r][col];
                o3 += part[q][2][r][col];
            }
            const int rowi = r0 + r;
            g_msg1[rowi * Dd + col] = o1;
            g_msg2[rowi * Dd + col] = o2;
            g_o1[rowi * Dd + col]   = o3;
        }
    }
}

// ===========================================================================
// Kernel 3 (fused): masked max over senders + add msg1, then
//   ret = o1 + msgs @ W_o2 + b_o2.
// Block = (b, 4 destination cols), 512 blocks x 256 threads.
// ===========================================================================
__global__ __launch_bounds__(256)
void maxfinal_kernel(const int* __restrict__ adj,
                     const float* __restrict__ Wo2,
                     const float* __restrict__ bo2,
                     float* __restrict__ out)      // [B*N,128]
{
    __shared__ int mask[Nn];
    __shared__ float red[2][4][128];
    __shared__ float ms[4][128];
    __shared__ float pg[4][128];
    const int blk = blockIdx.x;          // 0..511
    const int b   = blk >> 6;
    const int j0  = (blk & 63) * 4;
    const int tid = threadIdx.x;
    const int d   = tid & 127;
    const int ih  = tid >> 7;

    // 4-bit adjacency mask per sender i
    {
        const int* p = adj + ((size_t)(b * Nn + tid) * Nn + j0);
        const int4 a = *(const int4*)p;
        mask[tid] = (a.x > 0) | ((a.y > 0) << 1) | ((a.z > 0) << 2) | ((a.w > 0) << 3);
    }
    __syncthreads();

    const float* m2 = g_msg2 + (size_t)(b * (Nn + 1)) * Dd + d;
    const float vv = m2[Nn * Dd];        // virtual node always connected
    float vj[4] = {vv, vv, vv, vv};

#pragma unroll 4
    for (int ii = 0; ii < 128; ++ii) {
        const int i = ih * 128 + ii;
        const float x = m2[i * Dd];
        const int mk = mask[i];
#pragma unroll
        for (int q = 0; q < 4; ++q)
            if (mk & (1 << q)) vj[q] = fmaxf(vj[q], x);
    }
#pragma unroll
    for (int q = 0; q < 4; ++q) red[ih][q][d] = vj[q];
    __syncthreads();

    if (ih == 0) {
#pragma unroll
        for (int q = 0; q < 4; ++q)
            ms[q][d] = g_msg1[(size_t)(b * (Nn + 1) + j0 + q) * Dd + d]
                     + fmaxf(red[0][q][d], red[1][q][d]);
    }
    __syncthreads();

    // GEMM: each half-group handles 64 k
    float acc[4] = {0.f, 0.f, 0.f, 0.f};
    const int kb = ih * 64;
#pragma unroll 4
    for (int kk = 0; kk < 64; ++kk) {
        const int k = kb + kk;
        const float w = Wo2[k * Dd + d];
#pragma unroll
        for (int q = 0; q < 4; ++q) acc[q] = fmaf(ms[q][k], w, acc[q]);
    }
    if (ih) {
#pragma unroll
        for (int q = 0; q < 4; ++q) pg[q][d] = acc[q];
    }
    __syncthreads();
    if (!ih) {
        const float bb = bo2[d];
#pragma unroll
        for (int q = 0; q < 4; ++q)
            out[(size_t)(b * Nn + j0 + q) * Dd + d] =
                acc[q] + pg[q][d] + g_o1[(size_t)(b * (Nn + 1) + j0 + q) * Dd + d] + bb;
    }
}

// ===========================================================================
extern "C" void kernel_launch(void* const* d_in, const int* in_sizes, int n_in,
                              void* d_out, int out_size)
{
    const float* node_fts = (const float*)d_in[0];
    const float* edge_fts = (const float*)d_in[1];
    const int*   adj_mat  = (const int*)d_in[3];
    const float* hidden   = (const float*)d_in[4];
    const float* e_hidden = (const float*)d_in[5];
    const float* We   = (const float*)d_in[6];
    const float* be   = (const float*)d_in[7];
    const float* W_m1 = (const float*)d_in[8];
    const float* b_m1 = (const float*)d_in[9];
    const float* W_m2 = (const float*)d_in[10];
    const float* b_m2 = (const float*)d_in[11];
    const float* W_o1 = (const float*)d_in[12];
    const float* b_o1 = (const float*)d_in[13];
    const float* W_o2 = (const float*)d_in[14];
    const float* b_o2 = (const float*)d_in[15];

    float* ret_out = (float*)d_out;
    float* et_out  = (float*)d_out + Bq * Nn * Dd;

    // one-time host-side resources (created on the uncaptured correctness call)
    static cudaStream_t s_chain = nullptr;
    static cudaEvent_t ev_fork = nullptr, ev_join = nullptr;
    if (!s_chain) {
        cudaStreamCreateWithFlags(&s_chain, cudaStreamNonBlocking);
        cudaEventCreateWithFlags(&ev_fork, cudaEventDisableTiming);
        cudaEventCreateWithFlags(&ev_join, cudaEventDisableTiming);
        cudaFuncSetAttribute(et_mma_kernel, cudaFuncAttributeMaxDynamicSharedMemorySize, SMEM_ET);
    }

    // fork: MPNN chain runs concurrently with the big et GEMM
    cudaEventRecord(ev_fork, 0);
    cudaStreamWaitEvent(s_chain, ev_fork, 0);
    msgs_gemm_kernel<<<NROWS / 8, 512, 0, s_chain>>>(node_fts, hidden,
                                                     W_m1, b_m1, W_m2, b_m2, W_o1, b_o1);
    maxfinal_kernel<<<Bq * Nn / 4, 256, 0, s_chain>>>(adj_mat, W_o2, b_o2, ret_out);
    cudaEventRecord(ev_join, s_chain);

    // et GEMM on the main stream (persistent, mma.sync fp16 single-term, 2 CTA/SM)
    et_mma_kernel<<<296, 256, SMEM_ET>>>(edge_fts, e_hidden, We, be, et_out);

    // join
    cudaStreamWaitEvent(0, ev_join, 0);
}

// round 8
// speedup vs baseline: 2.3793x; 1.0766x over previous
#include <cuda_runtime.h>
#include <cstdint>

// ---------------------------------------------------------------------------
// AlignedMPNN: B=8, N=256, F=128, D=128
// Output: ret [8,256,128] followed by et [8,256,256,128]
// ---------------------------------------------------------------------------

#define Bq 8
#define Nn 256
#define Ff 128
#define Dd 128
#define M_ET (Bq * Nn * Nn)          // 524288
#define NROWS (Bq * (Nn + 1))        // 2056
#define N_TILES2 (M_ET / 256)        // 2048 tiles of 256 rows

// scratch for MPNN chain
__device__ float g_msg1[NROWS * Dd];
__device__ float g_msg2[NROWS * Dd];
__device__ float g_o1[NROWS * Dd];

// ===========================================================================
// helpers
// ===========================================================================
__device__ __forceinline__ uint32_t smem_u32_of(const void* p) {
    uint32_t a;
    asm("{ .reg .u64 t; cvta.to.shared.u64 t, %1; cvt.u32.u64 %0, t; }" : "=r"(a) : "l"(p));
    return a;
}

#define STS128(a0, a1, a2, a3, addr) \
    asm volatile("st.shared.v4.b32 [%0], {%1, %2, %3, %4};" :: "r"(addr), "r"(a0), "r"(a1), "r"(a2), "r"(a3) : "memory")

#define LDS128F(v, addr) \
    asm volatile("ld.shared.v4.f32 {%0, %1, %2, %3}, [%4];" \
        : "=f"((v).x), "=f"((v).y), "=f"((v).z), "=f"((v).w) : "r"(addr))

#define LDSM4(r, addr) \
    asm volatile("ldmatrix.sync.aligned.m8n8.x4.shared.b16 {%0,%1,%2,%3}, [%4];" \
        : "=r"((r)[0]), "=r"((r)[1]), "=r"((r)[2]), "=r"((r)[3]) : "r"(addr))

#define LDSM2(r, addr) \
    asm volatile("ldmatrix.sync.aligned.m8n8.x2.shared.b16 {%0,%1}, [%2];" \
        : "=r"((r)[0]), "=r"((r)[1]) : "r"(addr))

#define MMA_F16(d, a, b) \
    asm volatile("mma.sync.aligned.m16n8k16.row.col.f32.f16.f16.f32 " \
        "{%0,%1,%2,%3}, {%4,%5,%6,%7}, {%8,%9}, {%0,%1,%2,%3};" \
        : "+f"((d)[0]), "+f"((d)[1]), "+f"((d)[2]), "+f"((d)[3]) \
        : "r"((a)[0]), "r"((a)[1]), "r"((a)[2]), "r"((a)[3]), "r"((b)[0]), "r"((b)[1]))

__device__ __forceinline__ void cp_async16(uint32_t dst, const void* src) {
    asm volatile("cp.async.cg.shared.global [%0], [%1], 16;"
                 :: "r"(dst), "l"(__cvta_generic_to_global(src)) : "memory");
}
#define CP_COMMIT() asm volatile("cp.async.commit_group;" ::: "memory")
#define CP_WAIT2()  asm volatile("cp.async.wait_group 2;" ::: "memory")

// f16 tile layout: 64B rows, unit u (0..3, 16B), XOR swizzle. (verified R6)
#define ASWZ64(r, u) ((uint32_t)((r) * 64 + (((u) ^ (((r) >> 1) & 3)) * 16)))

// pack two f32 -> f16x2 (x0 in low half)
__device__ __forceinline__ uint32_t cvt2h(float x0, float x1) {
    uint32_t r;
    asm("cvt.rn.f16x2.f32 %0, %1, %2;" : "=r"(r) : "f"(x1), "f"(x0));
    return r;
}

// ===========================================================================
// et GEMM: C[M,128] = A1[M,128k] @ W[0:128,:] + A2[M,128k] @ W[128:256,:] + be
// mma.sync fp16 single-term; 148 persistent CTAs x 512 threads, 1 CTA/SM.
// M-tile 256, warp grid 4x4 (64x32/warp), k-chunks of 32.
// A path: cp.async f32 -> 3-stage smem ring (issued 2 chunks ahead, per-thread
// self-consume) -> cvt f16 -> double-buffered f16 tiles -> ldmatrix -> MMA.
//
// smem (192KB):
//   [0      .. 65536)  W fp16: 8 k32-chunks (8KB each), ASWZ64 rows
//   [65536  .. 98304)  A f16: 2 bufs x 16KB (256 rows x 64B), ASWZ64
//   [98304  .. 196608) A f32 stage: 3 x 32KB (256 rows x 128B, XOR units)
// ===========================================================================
#define OFF_F16 65536
#define OFF_F32 98304
#define SMEM_ET 196608

__global__ __launch_bounds__(512, 1)
void et_mma_kernel(const float* __restrict__ A1,
                   const float* __restrict__ A2,
                   const float* __restrict__ W,     // [256,128] f32
                   const float* __restrict__ bias,  // [128]
                   float* __restrict__ C)           // [M,128]
{
    extern __shared__ char smem[];
    const uint32_t sb = smem_u32_of(smem);
    const int tid   = threadIdx.x;
    const int lane  = tid & 31;
    const int wid   = tid >> 5;
    const int warpM = wid >> 2;      // 0..3  -> rows warpM*64
    const int warpN = wid & 3;       // 0..3  -> cols warpN*32

    // ---- one-time W conversion into resident smem (fp16, [n][k]) ----
    {
        const int n = tid & 127;
        const int g = tid >> 7;                 // 0..3
#pragma unroll
        for (int t = 0; t < 8; ++t) {
            const int kk = g * 8 + t;           // 8-k unit index 0..31
            const int c  = kk >> 2;
            const int u  = kk & 3;
            float w[8];
#pragma unroll
            for (int j = 0; j < 8; ++j) w[j] = W[(kk * 8 + j) * 128 + n];
            uint32_t p0 = cvt2h(w[0], w[1]);
            uint32_t p1 = cvt2h(w[2], w[3]);
            uint32_t p2 = cvt2h(w[4], w[5]);
            uint32_t p3 = cvt2h(w[6], w[7]);
            STS128(p0, p1, p2, p3, sb + c * 8192 + ASWZ64(n, u));
        }
    }

    // ---- per-thread invariant addressing ----
    // ldmatrix A (x4)
    const int mat  = lane >> 3;
    const int row0 = warpM * 64 + (mat & 1) * 8 + (lane & 7);
    const int ah   = mat >> 1;
    const int xr   = (row0 >> 1) & 3;
    uint32_t aoffs[2];
#pragma unroll
    for (int s = 0; s < 2; ++s)
        aoffs[s] = (uint32_t)(row0 * 64 + (((2 * s + ah) ^ xr) * 16));

    // ldmatrix B (x2)
    const int ls = lane & 15;
    const int n0 = warpN * 32 + (ls & 7);
    const int ub = ls >> 3;
    const int xn = (n0 >> 1) & 3;
    uint32_t boffs[2];
#pragma unroll
    for (int s = 0; s < 2; ++s)
        boffs[s] = (uint32_t)(n0 * 64 + (((2 * s + ub) ^ xn) * 16));

    float2 biasv[4];
#pragma unroll
    for (int nt = 0; nt < 4; ++nt)
        biasv[nt] = *(const float2*)&bias[warpN * 32 + nt * 8 + (lane & 3) * 2];

    // A staging: 2 threads per row; each thread owns 4 x 16B units of its row.
    const int row  = tid >> 1;
    const int half = tid & 1;
    const uint32_t f32row = (uint32_t)(OFF_F32 + row * 128);
    uint32_t fu[4];
#pragma unroll
    for (int q = 0; q < 4; ++q)
        fu[q] = (uint32_t)((((half * 4 + q) ^ (row & 7)) * 16));
    const uint32_t sa0 = (uint32_t)OFF_F16 + ASWZ64(row, half * 2);
    const uint32_t sa1 = (uint32_t)OFF_F16 + ASWZ64(row, half * 2 + 1);
    const int goff = row * 128 + half * 16;

    __syncthreads();

    // ---- cp.async prologue: issue chunks 0 and 1 of first tile ----
    int tile = blockIdx.x;
#pragma unroll
    for (int pc = 0; pc < 2; ++pc) {
        if (tile < N_TILES2) {
            const float* p = A1 + (size_t)tile * 32768 + goff + pc * 32;
            const uint32_t d = sb + f32row + pc * 32768;
#pragma unroll
            for (int q = 0; q < 4; ++q) cp_async16(d + fu[q], p + q * 4);
        }
        CP_COMMIT();
    }

    int cons = 0;   // global chunk counter (stage = cons%3, f16 buf = cons&1)

    while (tile < N_TILES2) {
        float acc[4][4][4];
#pragma unroll
        for (int mt = 0; mt < 4; ++mt)
#pragma unroll
            for (int nt = 0; nt < 4; ++nt) {
                acc[mt][nt][0] = biasv[nt].x; acc[mt][nt][1] = biasv[nt].y;
                acc[mt][nt][2] = biasv[nt].x; acc[mt][nt][3] = biasv[nt].y;
            }

#pragma unroll 1
        for (int c = 0; c < 8; ++c) {
            // issue cp.async for chunk 2 ahead
            {
                int nt2 = tile, nc2 = c + 2;
                if (nc2 >= 8) { nc2 -= 8; nt2 += gridDim.x; }
                if (nt2 < N_TILES2) {
                    const float* base = (nc2 < 4) ? A1 : A2;
                    const float* p = base + (size_t)nt2 * 32768 + goff + (nc2 & 3) * 32;
                    const uint32_t d = sb + f32row + ((cons + 2) % 3) * 32768;
#pragma unroll
                    for (int q = 0; q < 4; ++q) cp_async16(d + fu[q], p + q * 4);
                }
                CP_COMMIT();
            }

            // wait for this chunk's f32 stage (self-written; no barrier needed)
            CP_WAIT2();

            // convert f32 stage -> f16 buf
            {
                const uint32_t s32 = sb + f32row + (cons % 3) * 32768;
                float4 v0, v1, v2, v3;
                LDS128F(v0, s32 + fu[0]);
                LDS128F(v1, s32 + fu[1]);
                LDS128F(v2, s32 + fu[2]);
                LDS128F(v3, s32 + fu[3]);
                uint32_t p0 = cvt2h(v0.x, v0.y), p1 = cvt2h(v0.z, v0.w);
                uint32_t p2 = cvt2h(v1.x, v1.y), p3 = cvt2h(v1.z, v1.w);
                uint32_t p4 = cvt2h(v2.x, v2.y), p5 = cvt2h(v2.z, v2.w);
                uint32_t p6 = cvt2h(v3.x, v3.y), p7 = cvt2h(v3.z, v3.w);
                const uint32_t fb = sb + (cons & 1) * 16384;
                STS128(p0, p1, p2, p3, fb + sa0);
                STS128(p4, p5, p6, p7, fb + sa1);
            }
            __syncthreads();

            // compute: 2 k16 steps x 16 MMA
            const uint32_t wb = sb + (uint32_t)(c * 8192);
            const uint32_t ab = sb + OFF_F16 + (cons & 1) * 16384 - OFF_F16
                              + (uint32_t)OFF_F16;  // = sb + OFF_F16 + buf*16384
#pragma unroll
            for (int s = 0; s < 2; ++s) {
                uint32_t Av[4][4], Bv[4][2];
#pragma unroll
                for (int mt = 0; mt < 4; ++mt) LDSM4(Av[mt], ab + aoffs[s] + mt * 1024);
#pragma unroll
                for (int nt = 0; nt < 4; ++nt) LDSM2(Bv[nt], wb + boffs[s] + nt * 512);
#pragma unroll
                for (int mt = 0; mt < 4; ++mt)
#pragma unroll
                    for (int nt = 0; nt < 4; ++nt) MMA_F16(acc[mt][nt], Av[mt], Bv[nt]);
            }
            ++cons;
        }

        // epilogue: direct STG (32B-sector aligned float2 stores)
        const size_t m0 = (size_t)tile * 256;
#pragma unroll
        for (int mt = 0; mt < 4; ++mt) {
            const size_t r0 = m0 + warpM * 64 + mt * 16 + (lane >> 2);
#pragma unroll
            for (int nt = 0; nt < 4; ++nt) {
                const int col = warpN * 32 + nt * 8 + (lane & 3) * 2;
                *(float2*)&C[r0 * 128 + col]       = make_float2(acc[mt][nt][0], acc[mt][nt][1]);
                *(float2*)&C[(r0 + 8) * 128 + col] = make_float2(acc[mt][nt][2], acc[mt][nt][3]);
            }
        }
        tile += gridDim.x;
    }
}

// ===========================================================================
// Kernel 2: msg1/msg2/o1 = nt @ {W_m1,W_m2,W_o1} + bias.
// 512 threads: col = tid&127, k-quarter = tid>>7 (64 k each) -> smem reduce.
// ===========================================================================
__global__ __launch_bounds__(512)
void msgs_gemm_kernel(const float* __restrict__ node,
                      const float* __restrict__ hidden,
                      const float* __restrict__ Wm1, const float* __restrict__ bm1,
                      const float* __restrict__ Wm2, const float* __restrict__ bm2,
                      const float* __restrict__ Wo1, const float* __restrict__ bo1)
{
    __shared__ float s[8][2 * Ff];
    __shared__ float part[3][3][8][128];   // [kq-1][which][row][col]
    const int r0  = blockIdx.x * 8;
    const int tid = threadIdx.x;
    const int col = tid & 127;
    const int kq  = tid >> 7;

    for (int t = tid; t < 8 * 256; t += 512) {
        const int r = t >> 8, k = t & 255;
        const int rowi = r0 + r;
        const int b = rowi / (Nn + 1);
        const int i = rowi % (Nn + 1);
        float v = 0.f;
        if (i < Nn)
            v = (k < Ff) ? node[(b * Nn + i) * Ff + k]
                         : hidden[(b * Nn + i) * Ff + (k - Ff)];
        s[r][k] = v;
    }
    __syncthreads();

    float a1[8], a2[8], a3[8];
#pragma unroll
    for (int r = 0; r < 8; ++r) { a1[r] = 0.f; a2[r] = 0.f; a3[r] = 0.f; }

    const int kbase = kq * 64;
#pragma unroll 4
    for (int kk = 0; kk < 64; ++kk) {
        const int k = kbase + kk;
        const float w1 = Wm1[k * Dd + col];
        const float w2 = Wm2[k * Dd + col];
        const float w3 = Wo1[k * Dd + col];
#pragma unroll
        for (int r = 0; r < 8; ++r) {
            const float sv = s[r][k];
            a1[r] = fmaf(sv, w1, a1[r]);
            a2[r] = fmaf(sv, w2, a2[r]);
            a3[r] = fmaf(sv, w3, a3[r]);
        }
    }

    if (kq) {
#pragma unroll
        for (int r = 0; r < 8; ++r) {
            part[kq - 1][0][r][col] = a1[r];
            part[kq - 1][1][r][col] = a2[r];
            part[kq - 1][2][r][col] = a3[r];
        }
    }
    __syncthreads();

    if (kq == 0) {
        const float bb1 = bm1[col], bb2 = bm2[col], bb3 = bo1[col];
#pragma unroll
        for (int r = 0; r < 8; ++r) {
            float o1 = a1[r] + bb1, o2 = a2[r] + bb2, o3 = a3[r] + bb3;
#pragma unroll
            for (int q = 0; q < 3; ++q) {
                o1 += part[q][0][r][col];
                o2 += part[q][1][r][col];
                o3 += part[q][2][r][col];
            }
            const int rowi = r0 + r;
            g_msg1[rowi * Dd + col] = o1;
            g_msg2[rowi * Dd + col] = o2;
            g_o1[rowi * Dd + col]   = o3;
        }
    }
}

// ===========================================================================
// Kernel 3 (fused): masked max over senders + add msg1, then
//   ret = o1 + msgs @ W_o2 + b_o2.
// Block = (b, 4 destination cols), 512 blocks x 256 threads.
// ===========================================================================
__global__ __launch_bounds__(256)
void maxfinal_kernel(const int* __restrict__ adj,
                     const float* __restrict__ Wo2,
                     const float* __restrict__ bo2,
                     float* __restrict__ out)      // [B*N,128]
{
    __shared__ int mask[Nn];
    __shared__ float red[2][4][128];
    __shared__ float ms[4][128];
    __shared__ float pg[4][128];
    const int blk = blockIdx.x;          // 0..511
    const int b   = blk >> 6;
    const int j0  = (blk & 63) * 4;
    const int tid = threadIdx.x;
    const int d   = tid & 127;
    const int ih  = tid >> 7;

    // 4-bit adjacency mask per sender i
    {
        const int* p = adj + ((size_t)(b * Nn + tid) * Nn + j0);
        const int4 a = *(const int4*)p;
        mask[tid] = (a.x > 0) | ((a.y > 0) << 1) | ((a.z > 0) << 2) | ((a.w > 0) << 3);
    }
    __syncthreads();

    const float* m2 = g_msg2 + (size_t)(b * (Nn + 1)) * Dd + d;
    const float vv = m2[Nn * Dd];        // virtual node always connected
    float vj[4] = {vv, vv, vv, vv};

#pragma unroll 4
    for (int ii = 0; ii < 128; ++ii) {
        const int i = ih * 128 + ii;
        const float x = m2[i * Dd];
        const int mk = mask[i];
#pragma unroll
        for (int q = 0; q < 4; ++q)
            if (mk & (1 << q)) vj[q] = fmaxf(vj[q], x);
    }
#pragma unroll
    for (int q = 0; q < 4; ++q) red[ih][q][d] = vj[q];
    __syncthreads();

    if (ih == 0) {
#pragma unroll
        for (int q = 0; q < 4; ++q)
            ms[q][d] = g_msg1[(size_t)(b * (Nn + 1) + j0 + q) * Dd + d]
                     + fmaxf(red[0][q][d], red[1][q][d]);
    }
    __syncthreads();

    // GEMM: each half-group handles 64 k
    float acc[4] = {0.f, 0.f, 0.f, 0.f};
    const int kb = ih * 64;
#pragma unroll 4
    for (int kk = 0; kk < 64; ++kk) {
        const int k = kb + kk;
        const float w = Wo2[k * Dd + d];
#pragma unroll
        for (int q = 0; q < 4; ++q) acc[q] = fmaf(ms[q][k], w, acc[q]);
    }
    if (ih) {
#pragma unroll
        for (int q = 0; q < 4; ++q) pg[q][d] = acc[q];
    }
    __syncthreads();
    if (!ih) {
        const float bb = bo2[d];
#pragma unroll
        for (int q = 0; q < 4; ++q)
            out[(size_t)(b * Nn + j0 + q) * Dd + d] =
                acc[q] + pg[q][d] + g_o1[(size_t)(b * (Nn + 1) + j0 + q) * Dd + d] + bb;
    }
}

// ===========================================================================
extern "C" void kernel_launch(void* const* d_in, const int* in_sizes, int n_in,
                              void* d_out, int out_size)
{
    const float* node_fts = (const float*)d_in[0];
    const float* edge_fts = (const float*)d_in[1];
    const int*   adj_mat  = (const int*)d_in[3];
    const float* hidden   = (const float*)d_in[4];
    const float* e_hidden = (const float*)d_in[5];
    const float* We   = (const float*)d_in[6];
    const float* be   = (const float*)d_in[7];
    const float* W_m1 = (const float*)d_in[8];
    const float* b_m1 = (const float*)d_in[9];
    const float* W_m2 = (const float*)d_in[10];
    const float* b_m2 = (const float*)d_in[11];
    const float* W_o1 = (const float*)d_in[12];
    const float* b_o1 = (const float*)d_in[13];
    const float* W_o2 = (const float*)d_in[14];
    const float* b_o2 = (const float*)d_in[15];

    float* ret_out = (float*)d_out;
    float* et_out  = (float*)d_out + Bq * Nn * Dd;

    // one-time host-side resources (created on the uncaptured correctness call)
    static cudaStream_t s_chain = nullptr;
    static cudaEvent_t ev_fork = nullptr, ev_join = nullptr;
    if (!s_chain) {
        cudaStreamCreateWithFlags(&s_chain, cudaStreamNonBlocking);
        cudaEventCreateWithFlags(&ev_fork, cudaEventDisableTiming);
        cudaEventCreateWithFlags(&ev_join, cudaEventDisableTiming);
        cudaFuncSetAttribute(et_mma_kernel, cudaFuncAttributeMaxDynamicSharedMemorySize, SMEM_ET);
    }

    // fork: MPNN chain runs concurrently with the big et GEMM
    cudaEventRecord(ev_fork, 0);
    cudaStreamWaitEvent(s_chain, ev_fork, 0);
    msgs_gemm_kernel<<<NROWS / 8, 512, 0, s_chain>>>(node_fts, hidden,
                                                     W_m1, b_m1, W_m2, b_m2, W_o1, b_o1);
    maxfinal_kernel<<<Bq * Nn / 4, 256, 0, s_chain>>>(adj_mat, W_o2, b_o2, ret_out);
    cudaEventRecord(ev_join, s_chain);

    // et GEMM on the main stream (persistent, cp.async 3-stage + fp16 mma)
    et_mma_kernel<<<148, 512, SMEM_ET>>>(edge_fts, e_hidden, We, be, et_out);

    // join
    cudaStreamWaitEvent(0, ev_join, 0);
}